// round 17
// baseline (speedup 1.0000x reference)
#include <cuda_runtime.h>
#include <cuda_bf16.h>
#include <cstdint>

// Holt-Winters additive triple smoothing (gamma unused; season static).
// Reference step (t>=1), carried as v = (f, tr) with f = smooth+trend:
//   e  = y - (sea + f);  tn = tr + ab*e;  fn = f + al*e + tn;  out = fn + sea
// (exact-arithmetic equivalent of the reference recurrence; R13-verified,
//  rel_err ~4e-7).
//
// R17 = R13 (the fastest kernel so far: per-row serial scan, 64-row
// single-warp blocks, 2 rows/thread ILP, packed float2 season table with a
// single shared index roll) + DEPTH-3 cp.async pipeline at C=16:
// NBUF=4 x 5KB staging buffers (25.6KB total smem -> full residency
// preserved, unlike R10's 37KB), cp.async.wait_group 2 keeps ~3 chunks of
// reads in flight per warp -> the per-warp DRAM stream never goes dark
// during the chain-bound compute phase (R13's 63%-DRAM duty-cycle gap).

constexpr int ROWS    = 64;   // rows per block
constexpr int THREADS = 32;   // one warp
constexpr int C       = 16;   // time-steps per chunk
constexpr int CH4     = C / 4;        // 4 float4 per row-chunk
constexpr int S       = 20;   // smem row stride (floats): 16B-aligned,
                              // (5r+g) mod 8 distinct per 8-lane phase
constexpr int NCH     = 32;   // 512/16
constexpr int NBUF    = 4;    // depth-3 prefetch

__device__ __forceinline__ uint32_t smem_u32(const void* p) {
    return (uint32_t)__cvta_generic_to_shared(p);
}
__device__ __forceinline__ void cp_async16(uint32_t dst, const void* src) {
    asm volatile("cp.async.cg.shared.global [%0], [%1], 16;\n"
                 :: "r"(dst), "l"(src) : "memory");
}
__device__ __forceinline__ void cp_commit() {
    asm volatile("cp.async.commit_group;\n" ::: "memory");
}
template <int N>
__device__ __forceinline__ void cp_wait() {
    asm volatile("cp.async.wait_group %0;\n" :: "n"(N) : "memory");
}

// 6-op step on the (f, trend) carry.
__device__ __forceinline__ float hw_step_f(float y, float sea,
                                           float& f, float& tr,
                                           float al, float ab)
{
    float e  = y - (sea + f);
    float tn = fmaf(ab, e, tr);
    float fn = fmaf(al, e, f) + tn;
    tr = tn;
    f  = fn;
    return fn + sea;
}

__device__ __forceinline__ void issue_prefetch(
    int ch, int lane, int row0, int T,
    const float* __restrict__ series, float (&s_in)[NBUF][ROWS * S])
{
    const float* src = series + (size_t)ch * C;
    float* bufp = s_in[ch & (NBUF - 1)];
    #pragma unroll
    for (int k = 0; k < (ROWS * CH4) / THREADS; ++k) {   // 8
        int q  = k * THREADS + lane;
        int r  = q >> 2;
        int f4 = q & 3;
        cp_async16(smem_u32(&bufp[r * S + f4 * 4]),
                   src + (size_t)(row0 + r) * T + f4 * 4);
    }
}

__global__ __launch_bounds__(THREADS)
void hw_kernel(const float* __restrict__ series,
               const int*   __restrict__ shifts,
               const float* __restrict__ alpha_p,
               const float* __restrict__ beta_p,
               const float* __restrict__ season_g,
               const float* __restrict__ init_trend_p,
               float* __restrict__ out,
               int B, int T)
{
    __shared__ float  s_in [NBUF][ROWS * S];  // 4 x 5120 B
    __shared__ float  s_out[ROWS * S];        //     5120 B
    __shared__ float2 s_q2 [12 * 32];         // 3072 B: [j][lane] = (qA,qB)

    const int lane = threadIdx.x;
    const int row0 = blockIdx.x * ROWS;

    const float alpha      = *alpha_p;
    const float beta       = *beta_p;
    const float init_trend = *init_trend_p;
    const float ab = alpha * beta;

    // Packed season table: step t (>=1) of any row uses j = t mod 12;
    //   qX[j] = season[(j - shift_rowX) mod 12]
    {
        int shiftA = shifts[row0 + lane];
        int shiftB = shifts[row0 + lane + 32];
        int mA = (-shiftA) % 12; if (mA < 0) mA += 12;
        int mB = (-shiftB) % 12; if (mB < 0) mB += 12;
        #pragma unroll
        for (int j = 0; j < 12; ++j) {
            s_q2[j * 32 + lane] = make_float2(season_g[mA], season_g[mB]);
            mA = (mA + 1 == 12) ? 0 : mA + 1;
            mB = (mB + 1 == 12) ? 0 : mB + 1;
        }
    }

    const int t4 = T >> 2;
    float4* __restrict__ dstv = (float4*)out;

    float fA = 0.0f, trA = 0.0f;   // f = smooth + trend carry
    float fB = 0.0f, trB = 0.0f;
    int   j  = 1;                  // season index (t mod 12), shared rows

    // prologue: prefetch chunks 0..2 (three committed groups in flight)
    issue_prefetch(0, lane, row0, T, series, s_in);
    cp_commit();
    issue_prefetch(1, lane, row0, T, series, s_in);
    cp_commit();
    issue_prefetch(2, lane, row0, T, series, s_in);
    cp_commit();
    __syncwarp();    // season table visible before first compute

    #pragma unroll 1
    for (int ch = 0; ch < NCH; ++ch) {
        cp_wait<2>();    // chunk ch landed; ch+1, ch+2 may still fly
        __syncwarp();    // all lanes' waits done -> chunk ch visible; also
                         // orders all lanes' reads of buf (ch-1) before the
                         // prefetch below overwrites buf (ch+3)%4 == (ch-1)%4

        if (ch + 3 < NCH) issue_prefetch(ch + 3, lane, row0, T, series, s_in);
        cp_commit();     // one group per iteration keeps wait<2> aligned

        // compute: two independent rows per thread (2x ILP on the chain)
        {
            const float* base = s_in[ch & (NBUF - 1)];
            const float4* rinA  = (const float4*)(base + lane * S);
            const float4* rinB  = (const float4*)(base + (lane + 32) * S);
            float4*       routA = (float4*)(s_out + lane * S);
            float4*       routB = (float4*)(s_out + (lane + 32) * S);

            #pragma unroll
            for (int g = 0; g < CH4; ++g) {
                float4 a = rinA[g];
                float4 b = rinB[g];
                float4 oa, ob;
                float2 s2;

                if (ch == 0 && g == 0) {
                    // t = 0: out = y0 + init_trend; carry f = y0 + trend
                    trA = init_trend; fA = a.x + init_trend;
                    trB = init_trend; fB = b.x + init_trend;
                    oa.x = fA;
                    ob.x = fB;
                } else {
                    s2 = s_q2[j * 32 + lane];
                    j  = (j + 1 == 12) ? 0 : j + 1;
                    oa.x = hw_step_f(a.x, s2.x, fA, trA, alpha, ab);
                    ob.x = hw_step_f(b.x, s2.y, fB, trB, alpha, ab);
                }
                s2 = s_q2[j * 32 + lane];
                j  = (j + 1 == 12) ? 0 : j + 1;
                oa.y = hw_step_f(a.y, s2.x, fA, trA, alpha, ab);
                ob.y = hw_step_f(b.y, s2.y, fB, trB, alpha, ab);

                s2 = s_q2[j * 32 + lane];
                j  = (j + 1 == 12) ? 0 : j + 1;
                oa.z = hw_step_f(a.z, s2.x, fA, trA, alpha, ab);
                ob.z = hw_step_f(b.z, s2.y, fB, trB, alpha, ab);

                s2 = s_q2[j * 32 + lane];
                j  = (j + 1 == 12) ? 0 : j + 1;
                oa.w = hw_step_f(a.w, s2.x, fA, trA, alpha, ab);
                ob.w = hw_step_f(b.w, s2.y, fB, trB, alpha, ab);

                routA[g] = oa;
                routB[g] = ob;
            }
        }
        __syncwarp();    // s_out complete across lanes

        // store: 4 lanes = one row's 64B (2 full sectors); 8 rows/instr
        #pragma unroll
        for (int k = 0; k < (ROWS * CH4) / THREADS; ++k) {   // 8
            int q  = k * THREADS + lane;
            int r  = q >> 2;
            int f4 = q & 3;
            const float4* p = (const float4*)(s_out + r * S) + f4;
            dstv[(size_t)(row0 + r) * t4 + ch * CH4 + f4] = *p;
        }
        // next iteration's top __syncwarp orders these s_out reads before
        // the next compute overwrites s_out.
    }
}

// Generic fallback (shape-safe) for any B/T/slen — reference formulation.
__global__ __launch_bounds__(256)
void hw_kernel_generic(const float* __restrict__ series,
                       const int*   __restrict__ shifts,
                       const float* __restrict__ alpha_p,
                       const float* __restrict__ beta_p,
                       const float* __restrict__ season_g,
                       const float* __restrict__ init_trend_p,
                       float* __restrict__ out,
                       int B, int T, int slen)
{
    int row = blockIdx.x * blockDim.x + threadIdx.x;
    if (row >= B) return;
    const float alpha = *alpha_p, beta = *beta_p;
    const float oma = 1.0f - alpha, omb = 1.0f - beta;
    int shift = shifts[row];
    int idx = (1 - shift) % slen; if (idx < 0) idx += slen;
    const float* src = series + (size_t)row * T;
    float* dst = out + (size_t)row * T;
    float smooth = src[0], trend = *init_trend_p;
    dst[0] = smooth + trend;
    for (int t = 1; t < T; ++t) {
        float sea = season_g[idx];
        idx = (idx + 1 == slen) ? 0 : idx + 1;
        float sn = alpha * (src[t] - sea) + oma * (smooth + trend);
        float tn = beta * (sn - smooth) + omb * trend;
        dst[t] = sn + tn + sea;
        smooth = sn; trend = tn;
    }
}

extern "C" void kernel_launch(void* const* d_in, const int* in_sizes, int n_in,
                              void* d_out, int out_size)
{
    // 0: series f32 [B*T]   1: shifts i32 [B]   2: alpha   3: beta
    // 4: gamma (unused)     5: init_season [SLEN]   6: init_trend   7: n_preds
    const float* series     = (const float*)d_in[0];
    const int*   shifts     = (const int*)  d_in[1];
    const float* alpha_p    = (const float*)d_in[2];
    const float* beta_p     = (const float*)d_in[3];
    const float* season     = (const float*)d_in[5];
    const float* init_trend = (const float*)d_in[6];
    float* out = (float*)d_out;

    int B    = in_sizes[1];
    int T    = in_sizes[0] / B;      // 512
    int slen = in_sizes[5];          // 12

    if (slen == 12 && T == 512 && (B % ROWS) == 0) {
        int blocks = B / ROWS;       // 1024
        hw_kernel<<<blocks, THREADS>>>(series, shifts, alpha_p, beta_p,
                                       season, init_trend, out, B, T);
    } else {
        int threads = 256;
        int blocks  = (B + threads - 1) / threads;
        hw_kernel_generic<<<blocks, threads>>>(series, shifts, alpha_p, beta_p,
                                               season, init_trend, out,
                                               B, T, slen);
    }
}